// round 17
// baseline (speedup 1.0000x reference)
#include <cuda_runtime.h>
#include <cstdint>

// SequentialLoraA — adapter-major, software-pipelined streaming mainloop.
//   y_large[b,r] = sum_d x[b,d]     * A_large[wids_large[b], d, r]   (r<64)
//   y_small[b,r] = sum_d x[256+b,d] * A_small[wids_small[b], d, r]   (r<16)
// All f16 tensors arrive as FLOAT32. Output f32: y_large (256*64) then
// y_small (256*16).
//
// Grid = 128*4 large (adapter, 16-col chunk) CTAs + 128 small adapter CTAs.
// Each CTA inline-buckets its samples, stages their full x rows into smem
// once per pass, then streams its 256KB adapter chunk with a rotating
// two-batch register pipeline (8 LDG.128 issued ahead of each drain) so
// A-loads never fall out of flight. A is read with L1::no_allocate.

#define D_DIM    4096
#define B_LARGE  256
#define B_SMALL  256
#define R_LARGE  64
#define R_SMALL  16
#define N_ADAPT  128

// dynamic smem layout (floats):
//   [0, 4*4096)            sxs: x rows for up to G=4 samples (64 KB)
//   [16384, 16384+512)     wsum: 8 warps * 4 samples * 16 cols (2 KB)
//   then: s_list[256] (int), s_cnt (int)
#define SMEM_FLOATS (4 * 4096 + 512 + 257)

__device__ __forceinline__ float4 ldg_stream(const float* p) {
    float4 v;
    asm volatile("ld.global.nc.L1::no_allocate.v4.f32 {%0,%1,%2,%3}, [%4];"
                 : "=f"(v.x), "=f"(v.y), "=f"(v.z), "=f"(v.w) : "l"(p));
    return v;
}

// Geometry: CTA owns 16 output columns over full d (4096 rows).
// Per warp-step: 8 rows (rowsub = lane>>2) x 16 cols (col = (lane&3)*4).
// Warp covers d in [warp*512, warp*512+512): 64 steps = 8 blocks x 8.

template<int G>
__device__ __forceinline__ void do_pass(
    bool is_large, const float* __restrict__ A, const float* __restrict__ x,
    const int* bidx, int gcnt, int rc,
    float* __restrict__ sxs, float* __restrict__ wsum,
    float* __restrict__ out, int warp, int lane, int tid)
{
    const int stride = is_large ? R_LARGE : R_SMALL;
    const int col    = (lane & 3) * 4;
    const int rowsub = lane >> 2;
    const int dbase  = warp * 512 + rowsub;

    // ---- stage full x rows for the group (one barrier pair per pass) ----
    __syncthreads();                      // smem free (prev pass done)
    #pragma unroll
    for (int s = 0; s < G; ++s) {
        const int b  = bidx[(s < gcnt) ? s : 0];
        const int xb = is_large ? b : (B_LARGE + b);
        const float4* xr = (const float4*)(x + (size_t)xb * D_DIM);
        float4*       sr = (float4*)(sxs + s * D_DIM);
        #pragma unroll
        for (int k = 0; k < 4; ++k) sr[tid + 256 * k] = xr[tid + 256 * k];
    }
    __syncthreads();

    float4 acc[G];
    #pragma unroll
    for (int s = 0; s < G; ++s) acc[s] = make_float4(0.f, 0.f, 0.f, 0.f);

    // ---- rotating two-batch pipeline: loads always >= 8 in flight ----
    float4 v[2][8];
    #pragma unroll
    for (int j = 0; j < 8; ++j)
        v[0][j] = ldg_stream(A + (size_t)(dbase + j * 8) * stride + col);

    #pragma unroll
    for (int blk = 0; blk < 8; ++blk) {
        const int cur = blk & 1;
        if (blk < 7) {
            #pragma unroll
            for (int j = 0; j < 8; ++j) {
                const int d = dbase + ((blk + 1) * 8 + j) * 8;
                v[cur ^ 1][j] = ldg_stream(A + (size_t)d * stride + col);
            }
        }
        #pragma unroll
        for (int j = 0; j < 8; ++j) {
            const int d = dbase + (blk * 8 + j) * 8;
            #pragma unroll
            for (int s = 0; s < G; ++s) {
                const float xs = sxs[s * D_DIM + d];
                acc[s].x = fmaf(xs, v[cur][j].x, acc[s].x);
                acc[s].y = fmaf(xs, v[cur][j].y, acc[s].y);
                acc[s].z = fmaf(xs, v[cur][j].z, acc[s].z);
                acc[s].w = fmaf(xs, v[cur][j].w, acc[s].w);
            }
        }
    }

    // ---- reduce over the 8 row-groups (lane bits 2..4) ----
    #pragma unroll
    for (int s = 0; s < G; ++s) {
        #pragma unroll
        for (int m = 4; m <= 16; m <<= 1) {
            acc[s].x += __shfl_xor_sync(0xffffffffu, acc[s].x, m);
            acc[s].y += __shfl_xor_sync(0xffffffffu, acc[s].y, m);
            acc[s].z += __shfl_xor_sync(0xffffffffu, acc[s].z, m);
            acc[s].w += __shfl_xor_sync(0xffffffffu, acc[s].w, m);
        }
    }
    __syncthreads();
    if (lane < 4) {
        #pragma unroll
        for (int s = 0; s < G; ++s) {
            wsum[(warp * G + s) * 16 + col + 0] = acc[s].x;
            wsum[(warp * G + s) * 16 + col + 1] = acc[s].y;
            wsum[(warp * G + s) * 16 + col + 2] = acc[s].z;
            wsum[(warp * G + s) * 16 + col + 3] = acc[s].w;
        }
    }
    __syncthreads();

    if (tid < gcnt * 16) {
        const int s = tid >> 4, r = tid & 15;
        float sum = 0.f;
        #pragma unroll
        for (int ww = 0; ww < 8; ++ww) sum += wsum[(ww * G + s) * 16 + r];
        const int b = bidx[s];
        if (is_large) out[b * R_LARGE + rc + r] = sum;
        else          out[B_LARGE * R_LARGE + b * R_SMALL + r] = sum;
    }
}

__global__ __launch_bounds__(256, 2)
void lora_kernel(const float* __restrict__ x,
                 const int*   __restrict__ wl,
                 const int*   __restrict__ ws,
                 const float* __restrict__ A_large,
                 const float* __restrict__ A_small,
                 float*       __restrict__ out)
{
    extern __shared__ float smem[];
    float* sxs    = smem;                       // 4*4096 floats
    float* wsum   = smem + 4 * 4096;            // 512 floats
    int*   s_list = (int*)(smem + 4 * 4096 + 512);
    int*   s_cnt  = s_list + 256;

    const int c    = blockIdx.x;                // 0..639
    const int tid  = threadIdx.x;               // 0..255
    const int warp = tid >> 5;
    const int lane = tid & 31;

    const bool is_large = (c < N_ADAPT * 4);
    int w, rc = 0;
    const float* A;
    if (is_large) {
        w  = c >> 2;
        rc = (c & 3) * 16;
        A  = A_large + (size_t)w * D_DIM * R_LARGE + rc;
    } else {
        w = c - N_ADAPT * 4;
        A = A_small + (size_t)w * D_DIM * R_SMALL;
    }

    // ---- inline bucketing: find samples using adapter w ----
    if (tid == 0) *s_cnt = 0;
    __syncthreads();
    const int wv = is_large ? wl[tid] : ws[tid];
    if (wv == w) s_list[atomicAdd(s_cnt, 1)] = tid;
    __syncthreads();
    const int cnt = *s_cnt;
    if (cnt == 0) return;                       // unused adapter

    int g = 0;
    while (g < cnt) {
        const int rem  = cnt - g;
        const int take = (rem >= 3) ? ((rem >= 4) ? 4 : 3) : rem;
        int bidx[4];
        #pragma unroll
        for (int s = 0; s < 4; ++s) bidx[s] = (s < take) ? s_list[g + s] : 0;

        if (rem >= 3) {
            do_pass<4>(is_large, A, x, bidx, take, rc, sxs, wsum, out, warp, lane, tid);
        } else if (rem == 2) {
            do_pass<2>(is_large, A, x, bidx, 2, rc, sxs, wsum, out, warp, lane, tid);
        } else {
            do_pass<1>(is_large, A, x, bidx, 1, rc, sxs, wsum, out, warp, lane, tid);
        }
        g += take;
    }
}

extern "C" void kernel_launch(void* const* d_in, const int* in_sizes, int n_in,
                              void* d_out, int out_size)
{
    const float* x      = nullptr;
    const float* Alarge = nullptr;
    const float* Asmall = nullptr;
    const int*   widl   = nullptr;
    const int*   widsm  = nullptr;

    for (int i = 0; i < n_in; ++i) {
        const int sz = in_sizes[i];
        if (sz == 512 * D_DIM)                x      = (const float*)d_in[i];
        else if (sz == 128 * D_DIM * R_LARGE) Alarge = (const float*)d_in[i];
        else if (sz == 128 * D_DIM * R_SMALL) Asmall = (const float*)d_in[i];
        else if (sz == 256) { if (!widl) widl = (const int*)d_in[i];
                              else       widsm = (const int*)d_in[i]; }
    }

    static bool attr_set = false;
    const int smem_bytes = SMEM_FLOATS * 4;
    if (!attr_set) {
        cudaFuncSetAttribute(lora_kernel,
                             cudaFuncAttributeMaxDynamicSharedMemorySize,
                             smem_bytes);
        attr_set = true;
    }

    float* out = (float*)d_out;
    lora_kernel<<<N_ADAPT * 4 + N_ADAPT, 256, smem_bytes>>>(
        x, widl, widsm, Alarge, Asmall, out);
}